// round 5
// baseline (speedup 1.0000x reference)
#include <cuda_runtime.h>
#include <cuda_bf16.h>
#include <stdint.h>

// Int8SymmetricLinear via int8 IMMA (mma.m16n8k32.s8) on sm_103.
// out[M,N] = wscale[n] * (X[M,K] @ W[N,K]^T) + bias[n]
// W: true int8 (arrives as int32) -> exact.
// X: per-row 16-bit fixed point: x = s_m * q16, q16 = 256*q_hi + q_lo (int8 pair).
//   acc_hi = q_hi @ W, acc_lo = q_lo @ W (int32, exact)
//   out = s_m*(256*acc_hi + acc_lo)*wscale + bias   (rel err ~3e-5)

#define MDIM 8192
#define NDIM 11008
#define KDIM 4096

__device__ __align__(16) int8_t g_qhi[(size_t)MDIM * KDIM];
__device__ __align__(16) int8_t g_qlo[(size_t)MDIM * KDIM];
__device__ __align__(16) int8_t g_wq [(size_t)NDIM * KDIM];
__device__ float g_s[MDIM];

// ---------------- prep: rowmax + quantize X ----------------

__global__ void __launch_bounds__(256)
prep_x_kernel(const float* __restrict__ X)
{
    __shared__ float rowbuf[KDIM];
    __shared__ float wmax[8];
    __shared__ float s_inv_sh, s_sh;
    const int m = blockIdx.x;
    const int tid = threadIdx.x;
    const float* xr = X + (size_t)m * KDIM;

    float mx = 0.0f;
#pragma unroll
    for (int i = 0; i < 4; i++) {
        float4 v = reinterpret_cast<const float4*>(xr)[tid + i * 256];
        reinterpret_cast<float4*>(rowbuf)[tid + i * 256] = v;
        mx = fmaxf(mx, fmaxf(fmaxf(fabsf(v.x), fabsf(v.y)), fmaxf(fabsf(v.z), fabsf(v.w))));
    }
#pragma unroll
    for (int o = 16; o > 0; o >>= 1)
        mx = fmaxf(mx, __shfl_xor_sync(0xFFFFFFFF, mx, o));
    if ((tid & 31) == 0) wmax[tid >> 5] = mx;
    __syncthreads();
    if (tid == 0) {
        float t = wmax[0];
#pragma unroll
        for (int i = 1; i < 8; i++) t = fmaxf(t, wmax[i]);
        float si = (t > 0.0f) ? (32512.0f / t) : 0.0f;
        s_inv_sh = si;
        s_sh = (t > 0.0f) ? (t / 32512.0f) : 0.0f;
        g_s[m] = s_sh;
    }
    __syncthreads();
    const float si = s_inv_sh;

#pragma unroll
    for (int i = 0; i < 4; i++) {
        const int base = (tid + i * 256) * 4;
        char4 h4, l4;
#pragma unroll
        for (int j = 0; j < 4; j++) {
            int q = __float2int_rn(rowbuf[base + j] * si);
            int hi = (q + 128) >> 8;           // floor((q+128)/256) -> hi in [-127,127]
            int lo = q - (hi << 8);            // lo in [-128,127]
            ((signed char*)&h4)[j] = (signed char)hi;
            ((signed char*)&l4)[j] = (signed char)lo;
        }
        *reinterpret_cast<char4*>(g_qhi + (size_t)m * KDIM + base) = h4;
        *reinterpret_cast<char4*>(g_qlo + (size_t)m * KDIM + base) = l4;
    }
}

__global__ void __launch_bounds__(256)
prep_w_kernel(const int* __restrict__ W)
{
    // each thread packs 16 int32 -> 16 int8
    size_t i16 = (size_t)blockIdx.x * 256 + threadIdx.x;
    const int4* src = reinterpret_cast<const int4*>(W) + i16 * 4;
    uint32_t o[4];
#pragma unroll
    for (int j = 0; j < 4; j++) {
        int4 v = src[j];
        o[j] = (uint32_t)(v.x & 0xff) | ((uint32_t)(v.y & 0xff) << 8) |
               ((uint32_t)(v.z & 0xff) << 16) | ((uint32_t)(v.w & 0xff) << 24);
    }
    reinterpret_cast<uint4*>(g_wq)[i16] = make_uint4(o[0], o[1], o[2], o[3]);
}

// ---------------- GEMM ----------------

#define BM 128
#define BN 128
#define BK 128                       // int8 elems per chunk -> 128B rows
#define TILE_B (128 * 128)           // 16KB
#define OFF_HI 0
#define OFF_LO TILE_B
#define OFF_B  (2 * TILE_B)
#define STAGE_B (3 * TILE_B)         // 48KB
#define NSTAGE 3
#define SMEM_SZ (NSTAGE * STAGE_B)   // 144KB

static __device__ __forceinline__ uint32_t smem_u32(const void* p) {
    uint32_t a;
    asm("{ .reg .u64 t; cvta.to.shared.u64 t, %1; cvt.u32.u64 %0, t; }" : "=r"(a) : "l"(p));
    return a;
}
static __device__ __forceinline__ void cp16(uint32_t saddr, const void* g) {
    asm volatile("cp.async.cg.shared.global [%0], [%1], 16;" :: "r"(saddr), "l"(g));
}
static __device__ __forceinline__ void cp_commit() {
    asm volatile("cp.async.commit_group;" ::: "memory");
}
template <int N_>
static __device__ __forceinline__ void cp_wait() {
    asm volatile("cp.async.wait_group %0;" :: "n"(N_) : "memory");
}
static __device__ __forceinline__ void ldm4(uint32_t addr, uint32_t* r) {
    asm volatile("ldmatrix.sync.aligned.m8n8.x4.shared.b16 {%0,%1,%2,%3}, [%4];"
                 : "=r"(r[0]), "=r"(r[1]), "=r"(r[2]), "=r"(r[3]) : "r"(addr));
}
static __device__ __forceinline__ void imma16832(int* c, const uint32_t* a,
                                                 uint32_t b0, uint32_t b1) {
    asm volatile(
        "mma.sync.aligned.m16n8k32.row.col.s32.s8.s8.s32 "
        "{%0,%1,%2,%3}, {%4,%5,%6,%7}, {%8,%9}, {%0,%1,%2,%3};"
        : "+r"(c[0]), "+r"(c[1]), "+r"(c[2]), "+r"(c[3])
        : "r"(a[0]), "r"(a[1]), "r"(a[2]), "r"(a[3]), "r"(b0), "r"(b1));
}
// row-stride 128B, 16B slots, XOR-8 swizzle
static __device__ __forceinline__ uint32_t sw_addr(uint32_t base, int row, int slot) {
    return base + row * 128 + ((slot ^ (row & 7)) << 4);
}

extern __shared__ char smem_raw[];

__global__ void __launch_bounds__(512, 1)
gemm_s8_kernel(const float* __restrict__ Wscale,
               const float* __restrict__ Bias,
               float* __restrict__ Out)
{
    const int tid  = threadIdx.x;
    const int lane = tid & 31;
    const int wid  = tid >> 5;            // 0..15
    const int warp_m = wid >> 2;          // 0..3 -> m base 32*warp_m
    const int warp_n = wid & 3;           // 0..3 -> n base 32*warp_n
    const int bm = blockIdx.y * BM;
    const int bn = blockIdx.x * BN;
    const uint32_t sb = smem_u32(smem_raw);

    // loader: 512 threads, per tile 2 slots each (1024 slots/tile)
    const int ld_row  = tid >> 2;           // 0..127
    const int ld_s0   = (tid & 3) * 2;      // slots s0, s0+1

    int acc_hi[2][4][4], acc_lo[2][4][4];
#pragma unroll
    for (int mi = 0; mi < 2; mi++)
#pragma unroll
        for (int nf = 0; nf < 4; nf++)
#pragma unroll
            for (int q = 0; q < 4; q++) { acc_hi[mi][nf][q] = 0; acc_lo[mi][nf][q] = 0; }

    const int NCH = KDIM / BK;   // 32

    auto load_chunk = [&](int c, int stg) {
        const uint32_t st = sb + stg * STAGE_B;
        const size_t kbase = (size_t)c * BK;
        const size_t gx = (size_t)(bm + ld_row) * KDIM + kbase;
        const size_t gw = (size_t)(bn + ld_row) * KDIM + kbase;
        const uint32_t r128 = ld_row * 128;
#pragma unroll
        for (int u = 0; u < 2; u++) {
            const int s = ld_s0 + u;
            const uint32_t so = r128 + (((s ^ (ld_row & 7))) << 4);
            cp16(st + OFF_HI + so, g_qhi + gx + s * 16);
            cp16(st + OFF_LO + so, g_qlo + gx + s * 16);
            cp16(st + OFF_B  + so, g_wq  + gw + s * 16);
        }
    };

    load_chunk(0, 0); cp_commit();
    load_chunk(1, 1); cp_commit();
    load_chunk(2, 2); cp_commit();

    // ldmatrix addressing: group g = lane>>3 (matrix id), r = lane&7
    const int g  = lane >> 3;
    const int rr = lane & 7;
    const int row_off  = rr + (g & 1) * 8;   // + base row
    const int slot_off = g >> 1;             // + 2*kk

    for (int c = 0; c < NCH; c++) {
        cp_wait<2>();
        __syncthreads();
        const uint32_t st = sb + (c % NSTAGE) * STAGE_B;

#pragma unroll
        for (int kk = 0; kk < 4; kk++) {
            const int slot = 2 * kk + slot_off;
            uint32_t bf[2][4];
#pragma unroll
            for (int nb = 0; nb < 2; nb++) {
                const int row = 32 * warp_n + nb * 16 + row_off;
                ldm4(sw_addr(st + OFF_B, row, slot), bf[nb]);
            }
            uint32_t ah[2][4], al[2][4];
#pragma unroll
            for (int mi = 0; mi < 2; mi++) {
                const int row = 32 * warp_m + mi * 16 + row_off;
                ldm4(sw_addr(st + OFF_HI, row, slot), ah[mi]);
                ldm4(sw_addr(st + OFF_LO, row, slot), al[mi]);
            }
            // fragments: A = {r0,r1,r2,r3}; B n8-frag j: {r[j], r[j+2]}
#pragma unroll
            for (int mi = 0; mi < 2; mi++)
#pragma unroll
                for (int nb = 0; nb < 2; nb++) {
                    imma16832(acc_hi[mi][nb * 2 + 0], ah[mi], bf[nb][0], bf[nb][2]);
                    imma16832(acc_hi[mi][nb * 2 + 1], ah[mi], bf[nb][1], bf[nb][3]);
                    imma16832(acc_lo[mi][nb * 2 + 0], al[mi], bf[nb][0], bf[nb][2]);
                    imma16832(acc_lo[mi][nb * 2 + 1], al[mi], bf[nb][1], bf[nb][3]);
                }
        }

        __syncthreads();
        if (c + NSTAGE < NCH) load_chunk(c + NSTAGE, c % NSTAGE);
        cp_commit();
    }

    // ---- epilogue ----
#pragma unroll
    for (int mi = 0; mi < 2; mi++) {
        const int m0 = bm + 32 * warp_m + mi * 16 + (lane >> 2);
        const float s0 = g_s[m0];
        const float s1 = g_s[m0 + 8];
        float* orow0 = Out + (size_t)m0 * NDIM;
        float* orow1 = Out + (size_t)(m0 + 8) * NDIM;
#pragma unroll
        for (int nf = 0; nf < 4; nf++) {
            const int n = bn + 32 * warp_n + nf * 8 + (lane & 3) * 2;
            float2 ws = *reinterpret_cast<const float2*>(Wscale + n);
            float2 bi = *reinterpret_cast<const float2*>(Bias + n);
            const int* h = acc_hi[mi][nf];
            const int* l = acc_lo[mi][nf];
            float c0 = fmaf(256.0f, (float)h[0], (float)l[0]) * s0;
            float c1 = fmaf(256.0f, (float)h[1], (float)l[1]) * s0;
            float c2 = fmaf(256.0f, (float)h[2], (float)l[2]) * s1;
            float c3 = fmaf(256.0f, (float)h[3], (float)l[3]) * s1;
            float2 o0, o1;
            o0.x = fmaf(c0, ws.x, bi.x);
            o0.y = fmaf(c1, ws.y, bi.y);
            o1.x = fmaf(c2, ws.x, bi.x);
            o1.y = fmaf(c3, ws.y, bi.y);
            *reinterpret_cast<float2*>(orow0 + n) = o0;
            *reinterpret_cast<float2*>(orow1 + n) = o1;
        }
    }
}

// ---------------- launch ----------------

extern "C" void kernel_launch(void* const* d_in, const int* in_sizes, int n_in,
                              void* d_out, int out_size)
{
    const float* X      = (const float*)d_in[0];   // [M, K] fp32
    const int*   W      = (const int*)d_in[1];     // [N, K] int32 (int8 values)
    const float* Wscale = (const float*)d_in[2];   // [N] fp32
    const float* Bias   = (const float*)d_in[3];   // [N] fp32
    float*       Out    = (float*)d_out;           // [M, N] fp32

    prep_x_kernel<<<MDIM, 256>>>(X);
    prep_w_kernel<<<(size_t)NDIM * KDIM / (16 * 256), 256>>>(W);

    static int smem_set = 0;
    if (!smem_set) {
        cudaFuncSetAttribute(gemm_s8_kernel,
                             cudaFuncAttributeMaxDynamicSharedMemorySize, SMEM_SZ);
        smem_set = 1;
    }
    dim3 grid(NDIM / BN, MDIM / BM);   // 86 x 64
    gemm_s8_kernel<<<grid, 512, SMEM_SZ>>>(Wscale, Bias, Out);
}

// round 6
// speedup vs baseline: 6.0091x; 6.0091x over previous
#include <cuda_runtime.h>
#include <cuda_fp16.h>
#include <stdint.h>

// Int8SymmetricLinear via single-pass fp16 mma.sync on sm_103.
// out[M,N] = wscale[n] * (X[M,K] @ W[N,K]^T) + bias[n]
// W arrives as int32, values in [-127,127] -> EXACT in fp16.
// X fp32 rounded to fp16 (11-bit mantissa): output rel err ~2.5e-4 << 1e-3.
// fp32 accumulate in mma. One pass => half the MMA + half the LDSM of the
// bf16 hi/lo scheme. BM=BN=128, BK=64, 256 thr, 3-stage cp.async pipeline.

#define MDIM 8192
#define NDIM 11008
#define KDIM 4096

__device__ __align__(16) __half g_Xh[(size_t)MDIM * KDIM];
__device__ __align__(16) __half g_Wh[(size_t)NDIM * KDIM];

// ---------------- prep kernels ----------------

__global__ void __launch_bounds__(256)
prep_x_kernel(const float* __restrict__ X)
{
    size_t i4 = (size_t)blockIdx.x * 256 + threadIdx.x;   // unit of 4 elems
    float4 v = reinterpret_cast<const float4*>(X)[i4];
    uint2 o;
    __half2 p0 = __floats2half2_rn(v.x, v.y);
    __half2 p1 = __floats2half2_rn(v.z, v.w);
    o.x = *reinterpret_cast<uint32_t*>(&p0);
    o.y = *reinterpret_cast<uint32_t*>(&p1);
    reinterpret_cast<uint2*>(g_Xh)[i4] = o;
}

__global__ void __launch_bounds__(256)
prep_w_kernel(const int* __restrict__ W)
{
    size_t i4 = (size_t)blockIdx.x * 256 + threadIdx.x;
    int4 v = reinterpret_cast<const int4*>(W)[i4];
    uint2 o;
    __half2 p0 = __floats2half2_rn(__int2float_rn(v.x), __int2float_rn(v.y));
    __half2 p1 = __floats2half2_rn(__int2float_rn(v.z), __int2float_rn(v.w));
    o.x = *reinterpret_cast<uint32_t*>(&p0);
    o.y = *reinterpret_cast<uint32_t*>(&p1);
    reinterpret_cast<uint2*>(g_Wh)[i4] = o;
}

// ---------------- GEMM ----------------

#define BM 128
#define BN 128
#define BK 64                       // fp16 elems per chunk -> 128B rows
#define TILE_B (128 * 128)          // 16KB: 128 rows x 128B
#define OFF_A 0
#define OFF_B TILE_B
#define STAGE_B (2 * TILE_B)        // 32KB
#define NSTAGE 3
#define SMEM_SZ (NSTAGE * STAGE_B)  // 96KB

static __device__ __forceinline__ uint32_t smem_u32(const void* p) {
    uint32_t a;
    asm("{ .reg .u64 t; cvta.to.shared.u64 t, %1; cvt.u32.u64 %0, t; }" : "=r"(a) : "l"(p));
    return a;
}
static __device__ __forceinline__ void cp16(uint32_t saddr, const void* g) {
    asm volatile("cp.async.cg.shared.global [%0], [%1], 16;" :: "r"(saddr), "l"(g));
}
static __device__ __forceinline__ void cp_commit() {
    asm volatile("cp.async.commit_group;" ::: "memory");
}
template <int N_>
static __device__ __forceinline__ void cp_wait() {
    asm volatile("cp.async.wait_group %0;" :: "n"(N_) : "memory");
}
static __device__ __forceinline__ void ldm4(uint32_t addr, uint32_t* r) {
    asm volatile("ldmatrix.sync.aligned.m8n8.x4.shared.b16 {%0,%1,%2,%3}, [%4];"
                 : "=r"(r[0]), "=r"(r[1]), "=r"(r[2]), "=r"(r[3]) : "r"(addr));
}
static __device__ __forceinline__ void mma16816(float* c, const uint32_t* a, const uint32_t* b) {
    asm volatile(
        "mma.sync.aligned.m16n8k16.row.col.f32.f16.f16.f32 "
        "{%0,%1,%2,%3}, {%4,%5,%6,%7}, {%8,%9}, {%0,%1,%2,%3};"
        : "+f"(c[0]), "+f"(c[1]), "+f"(c[2]), "+f"(c[3])
        : "r"(a[0]), "r"(a[1]), "r"(a[2]), "r"(a[3]), "r"(b[0]), "r"(b[1]));
}
// row-stride 128B, 16B slots, XOR-8 swizzle
static __device__ __forceinline__ uint32_t sw_addr(uint32_t base, int row, int slot) {
    return base + row * 128 + ((slot ^ (row & 7)) << 4);
}

extern __shared__ char smem_raw[];

__global__ void __launch_bounds__(256, 2)
gemm_f16_kernel(const float* __restrict__ Wscale,
                const float* __restrict__ Bias,
                float* __restrict__ Out)
{
    const int tid    = threadIdx.x;
    const int lane   = tid & 31;
    const int wid    = tid >> 5;
    const int warp_m = wid >> 1;      // 0..3 -> m offset 32*warp_m
    const int warp_n = wid & 1;       // 0..1 -> n offset 64*warp_n
    const int bm = blockIdx.y * BM;
    const int bn = blockIdx.x * BN;
    const uint32_t sb = smem_u32(smem_raw);

    // loader mapping: 1024 16B-slots per tile, 4 per thread per tile
    const int ld_row0 = tid >> 3;         // +32 per step
    const int ld_slot = tid & 7;

    float acc[2][8][4];
#pragma unroll
    for (int i = 0; i < 2; i++)
#pragma unroll
        for (int j = 0; j < 8; j++)
#pragma unroll
            for (int q = 0; q < 4; q++) acc[i][j][q] = 0.0f;

    const int NCH = KDIM / BK;   // 64

    auto load_chunk = [&](int c, int stg) {
        const uint32_t st = sb + stg * STAGE_B;
        const size_t kt = (size_t)c * BK;
#pragma unroll
        for (int u = 0; u < 4; u++) {
            const int row = ld_row0 + u * 32;
            const uint32_t so = (uint32_t)(row * 128 + ((ld_slot ^ (row & 7)) << 4));
            const size_t gx = (size_t)(bm + row) * KDIM + kt + ld_slot * 8;
            const size_t gw = (size_t)(bn + row) * KDIM + kt + ld_slot * 8;
            cp16(st + OFF_A + so, g_Xh + gx);
            cp16(st + OFF_B + so, g_Wh + gw);
        }
    };

    load_chunk(0, 0); cp_commit();
    load_chunk(1, 1); cp_commit();
    load_chunk(2, 2); cp_commit();

    for (int c = 0; c < NCH; c++) {
        const int stg = c % NSTAGE;
        cp_wait<2>();
        __syncthreads();

        const uint32_t atl = sb + stg * STAGE_B + OFF_A;
        const uint32_t btl = sb + stg * STAGE_B + OFF_B;

#pragma unroll
        for (int k16 = 0; k16 < 4; k16++) {
            uint32_t bf[4][4];     // 4 n16-blocks
#pragma unroll
            for (int nb = 0; nb < 4; nb++) {
                const int row  = warp_n * 64 + nb * 16 + ((lane & 16) >> 1) + (lane & 7);
                const int slot = 2 * k16 + ((lane >> 3) & 1);
                ldm4(sw_addr(btl, row, slot), bf[nb]);
            }
            uint32_t af[2][4];
#pragma unroll
            for (int mi = 0; mi < 2; mi++) {
                const int row  = warp_m * 32 + mi * 16 + (lane & 15);
                const int slot = 2 * k16 + (lane >> 4);
                ldm4(sw_addr(atl, row, slot), af[mi]);
            }
#pragma unroll
            for (int mi = 0; mi < 2; mi++)
#pragma unroll
                for (int nb = 0; nb < 4; nb++) {
                    mma16816(acc[mi][nb * 2 + 0], af[mi], &bf[nb][0]);
                    mma16816(acc[mi][nb * 2 + 1], af[mi], &bf[nb][2]);
                }
        }

        __syncthreads();
        if (c + NSTAGE < NCH) load_chunk(c + NSTAGE, stg);
        cp_commit();
    }

    // ---- epilogue: scale + bias, float2 stores ----
    const int n_base = bn + warp_n * 64 + (lane & 3) * 2;
    float2 sc[8], bi[8];
#pragma unroll
    for (int nj = 0; nj < 8; nj++) {
        sc[nj] = *reinterpret_cast<const float2*>(Wscale + n_base + nj * 8);
        bi[nj] = *reinterpret_cast<const float2*>(Bias   + n_base + nj * 8);
    }
#pragma unroll
    for (int mi = 0; mi < 2; mi++) {
        const int m0 = bm + warp_m * 32 + mi * 16 + (lane >> 2);
#pragma unroll
        for (int nj = 0; nj < 8; nj++) {
            const int n = n_base + nj * 8;
            float2 o0, o1;
            o0.x = fmaf(acc[mi][nj][0], sc[nj].x, bi[nj].x);
            o0.y = fmaf(acc[mi][nj][1], sc[nj].y, bi[nj].y);
            o1.x = fmaf(acc[mi][nj][2], sc[nj].x, bi[nj].x);
            o1.y = fmaf(acc[mi][nj][3], sc[nj].y, bi[nj].y);
            *reinterpret_cast<float2*>(Out + (size_t)m0 * NDIM + n)       = o0;
            *reinterpret_cast<float2*>(Out + (size_t)(m0 + 8) * NDIM + n) = o1;
        }
    }
}

// ---------------- launch ----------------

extern "C" void kernel_launch(void* const* d_in, const int* in_sizes, int n_in,
                              void* d_out, int out_size)
{
    const float* X      = (const float*)d_in[0];   // [M, K] fp32
    const int*   W      = (const int*)d_in[1];     // [N, K] int32 (int8 values)
    const float* Wscale = (const float*)d_in[2];   // [N] fp32
    const float* Bias   = (const float*)d_in[3];   // [N] fp32
    float*       Out    = (float*)d_out;           // [M, N] fp32

    prep_x_kernel<<<(size_t)MDIM * KDIM / (256 * 4), 256>>>(X);
    prep_w_kernel<<<(size_t)NDIM * KDIM / (256 * 4), 256>>>(W);

    static int smem_set = 0;
    if (!smem_set) {
        cudaFuncSetAttribute(gemm_f16_kernel,
                             cudaFuncAttributeMaxDynamicSharedMemorySize, SMEM_SZ);
        smem_set = 1;
    }
    dim3 grid(NDIM / BN, MDIM / BM);   // 86 x 64
    gemm_f16_kernel<<<grid, 256, SMEM_SZ>>>(Wscale, Bias, Out);
}

// round 7
// speedup vs baseline: 6.3385x; 1.0548x over previous
#include <cuda_runtime.h>
#include <cuda_fp16.h>
#include <stdint.h>

// Int8SymmetricLinear via single-pass fp16 mma.sync on sm_103.
// out[M,N] = wscale[n] * (X[M,K] @ W[N,K]^T) + bias[n]
// W int32 in [-127,127] -> exact in fp16; X rounded to fp16 (rel err ~2e-4).
//
// Round 7: reduce smem LDSM traffic (the round-6 binding constraint).
// 128x128 CTA, 128 threads = 4 warps, each warp owns a 64x64 tile:
// ldmatrix:mma ratio drops 0.375 -> 0.25 (chip LDSM 33.6GB -> 22.5GB).
// 3-stage cp.async pipeline (96KB), 2 CTAs/SM.

#define MDIM 8192
#define NDIM 11008
#define KDIM 4096

__device__ __align__(16) __half g_Xh[(size_t)MDIM * KDIM];
__device__ __align__(16) __half g_Wh[(size_t)NDIM * KDIM];

// ---------------- prep kernels ----------------

__global__ void __launch_bounds__(256)
prep_x_kernel(const float* __restrict__ X)
{
    size_t i4 = (size_t)blockIdx.x * 256 + threadIdx.x;
    float4 v = reinterpret_cast<const float4*>(X)[i4];
    uint2 o;
    __half2 p0 = __floats2half2_rn(v.x, v.y);
    __half2 p1 = __floats2half2_rn(v.z, v.w);
    o.x = *reinterpret_cast<uint32_t*>(&p0);
    o.y = *reinterpret_cast<uint32_t*>(&p1);
    reinterpret_cast<uint2*>(g_Xh)[i4] = o;
}

__global__ void __launch_bounds__(256)
prep_w_kernel(const int* __restrict__ W)
{
    size_t i4 = (size_t)blockIdx.x * 256 + threadIdx.x;
    int4 v = reinterpret_cast<const int4*>(W)[i4];
    uint2 o;
    __half2 p0 = __floats2half2_rn(__int2float_rn(v.x), __int2float_rn(v.y));
    __half2 p1 = __floats2half2_rn(__int2float_rn(v.z), __int2float_rn(v.w));
    o.x = *reinterpret_cast<uint32_t*>(&p0);
    o.y = *reinterpret_cast<uint32_t*>(&p1);
    reinterpret_cast<uint2*>(g_Wh)[i4] = o;
}

// ---------------- GEMM ----------------

#define BM 128
#define BN 128
#define BK 64                       // fp16 elems per chunk -> 128B rows
#define TILE_B (128 * 128)          // 16KB
#define OFF_A 0
#define OFF_B TILE_B
#define STAGE_B (2 * TILE_B)        // 32KB
#define NSTAGE 3
#define SMEM_SZ (NSTAGE * STAGE_B)  // 96KB

static __device__ __forceinline__ uint32_t smem_u32(const void* p) {
    uint32_t a;
    asm("{ .reg .u64 t; cvta.to.shared.u64 t, %1; cvt.u32.u64 %0, t; }" : "=r"(a) : "l"(p));
    return a;
}
static __device__ __forceinline__ void cp16(uint32_t saddr, const void* g) {
    asm volatile("cp.async.cg.shared.global [%0], [%1], 16;" :: "r"(saddr), "l"(g));
}
static __device__ __forceinline__ void cp_commit() {
    asm volatile("cp.async.commit_group;" ::: "memory");
}
template <int N_>
static __device__ __forceinline__ void cp_wait() {
    asm volatile("cp.async.wait_group %0;" :: "n"(N_) : "memory");
}
static __device__ __forceinline__ void ldm4(uint32_t addr, uint32_t* r) {
    asm volatile("ldmatrix.sync.aligned.m8n8.x4.shared.b16 {%0,%1,%2,%3}, [%4];"
                 : "=r"(r[0]), "=r"(r[1]), "=r"(r[2]), "=r"(r[3]) : "r"(addr));
}
static __device__ __forceinline__ void mma16816(float* c, const uint32_t* a, const uint32_t* b) {
    asm volatile(
        "mma.sync.aligned.m16n8k16.row.col.f32.f16.f16.f32 "
        "{%0,%1,%2,%3}, {%4,%5,%6,%7}, {%8,%9}, {%0,%1,%2,%3};"
        : "+f"(c[0]), "+f"(c[1]), "+f"(c[2]), "+f"(c[3])
        : "r"(a[0]), "r"(a[1]), "r"(a[2]), "r"(a[3]), "r"(b[0]), "r"(b[1]));
}
// row-stride 128B, 16B slots, XOR-8 swizzle
static __device__ __forceinline__ uint32_t sw_addr(uint32_t base, int row, int slot) {
    return base + row * 128 + ((slot ^ (row & 7)) << 4);
}

extern __shared__ char smem_raw[];

__global__ void __launch_bounds__(128, 2)
gemm_f16_kernel(const float* __restrict__ Wscale,
                const float* __restrict__ Bias,
                float* __restrict__ Out)
{
    const int tid    = threadIdx.x;
    const int lane   = tid & 31;
    const int wid    = tid >> 5;      // 0..3
    const int warp_m = wid >> 1;      // 0..1 -> m offset 64*warp_m
    const int warp_n = wid & 1;       // 0..1 -> n offset 64*warp_n
    const int bm = blockIdx.y * BM;
    const int bn = blockIdx.x * BN;
    const uint32_t sb = smem_u32(smem_raw);

    // loader mapping: 1024 16B-slots per tile, 8 per thread per tile
    const int ld_row0 = tid >> 3;         // 0..15, +16 per step
    const int ld_slot = tid & 7;

    float acc[4][8][4];
#pragma unroll
    for (int i = 0; i < 4; i++)
#pragma unroll
        for (int j = 0; j < 8; j++)
#pragma unroll
            for (int q = 0; q < 4; q++) acc[i][j][q] = 0.0f;

    const int NCH = KDIM / BK;   // 64

    auto load_chunk = [&](int c, int stg) {
        const uint32_t st = sb + stg * STAGE_B;
        const size_t kt = (size_t)c * BK;
#pragma unroll
        for (int u = 0; u < 8; u++) {
            const int row = ld_row0 + u * 16;
            const uint32_t so = (uint32_t)(row * 128 + ((ld_slot ^ (row & 7)) << 4));
            const size_t gx = (size_t)(bm + row) * KDIM + kt + ld_slot * 8;
            const size_t gw = (size_t)(bn + row) * KDIM + kt + ld_slot * 8;
            cp16(st + OFF_A + so, g_Xh + gx);
            cp16(st + OFF_B + so, g_Wh + gw);
        }
    };

    load_chunk(0, 0); cp_commit();
    load_chunk(1, 1); cp_commit();
    load_chunk(2, 2); cp_commit();

    for (int c = 0; c < NCH; c++) {
        const int stg = c % NSTAGE;
        cp_wait<2>();
        __syncthreads();

        const uint32_t atl = sb + stg * STAGE_B + OFF_A;
        const uint32_t btl = sb + stg * STAGE_B + OFF_B;

#pragma unroll
        for (int k16 = 0; k16 < 4; k16++) {
            uint32_t bf[4][4];     // 4 n16-blocks -> 8 n8 frags
#pragma unroll
            for (int nb = 0; nb < 4; nb++) {
                const int row  = warp_n * 64 + nb * 16 + ((lane & 16) >> 1) + (lane & 7);
                const int slot = 2 * k16 + ((lane >> 3) & 1);
                ldm4(sw_addr(btl, row, slot), bf[nb]);
            }
            uint32_t af[4][4];     // 4 m16-blocks
#pragma unroll
            for (int mb = 0; mb < 4; mb++) {
                const int row  = warp_m * 64 + mb * 16 + (lane & 15);
                const int slot = 2 * k16 + (lane >> 4);
                ldm4(sw_addr(atl, row, slot), af[mb]);
            }
#pragma unroll
            for (int mb = 0; mb < 4; mb++)
#pragma unroll
                for (int nb = 0; nb < 4; nb++) {
                    mma16816(acc[mb][nb * 2 + 0], af[mb], &bf[nb][0]);
                    mma16816(acc[mb][nb * 2 + 1], af[mb], &bf[nb][2]);
                }
        }

        __syncthreads();
        if (c + NSTAGE < NCH) load_chunk(c + NSTAGE, stg);
        cp_commit();
    }

    // ---- epilogue: scale + bias, float2 stores ----
    const int n_base = bn + warp_n * 64 + (lane & 3) * 2;
    float2 sc[8], bi[8];
#pragma unroll
    for (int nj = 0; nj < 8; nj++) {
        sc[nj] = *reinterpret_cast<const float2*>(Wscale + n_base + nj * 8);
        bi[nj] = *reinterpret_cast<const float2*>(Bias   + n_base + nj * 8);
    }
#pragma unroll
    for (int mb = 0; mb < 4; mb++) {
        const int m0 = bm + warp_m * 64 + mb * 16 + (lane >> 2);
#pragma unroll
        for (int nj = 0; nj < 8; nj++) {
            const int n = n_base + nj * 8;
            float2 o0, o1;
            o0.x = fmaf(acc[mb][nj][0], sc[nj].x, bi[nj].x);
            o0.y = fmaf(acc[mb][nj][1], sc[nj].y, bi[nj].y);
            o1.x = fmaf(acc[mb][nj][2], sc[nj].x, bi[nj].x);
            o1.y = fmaf(acc[mb][nj][3], sc[nj].y, bi[nj].y);
            *reinterpret_cast<float2*>(Out + (size_t)m0 * NDIM + n)       = o0;
            *reinterpret_cast<float2*>(Out + (size_t)(m0 + 8) * NDIM + n) = o1;
        }
    }
}

// ---------------- launch ----------------

extern "C" void kernel_launch(void* const* d_in, const int* in_sizes, int n_in,
                              void* d_out, int out_size)
{
    const float* X      = (const float*)d_in[0];   // [M, K] fp32
    const int*   W      = (const int*)d_in[1];     // [N, K] int32 (int8 values)
    const float* Wscale = (const float*)d_in[2];   // [N] fp32
    const float* Bias   = (const float*)d_in[3];   // [N] fp32
    float*       Out    = (float*)d_out;           // [M, N] fp32

    prep_x_kernel<<<(size_t)MDIM * KDIM / (256 * 4), 256>>>(X);
    prep_w_kernel<<<(size_t)NDIM * KDIM / (256 * 4), 256>>>(W);

    static int smem_set = 0;
    if (!smem_set) {
        cudaFuncSetAttribute(gemm_f16_kernel,
                             cudaFuncAttributeMaxDynamicSharedMemorySize, SMEM_SZ);
        smem_set = 1;
    }
    dim3 grid(NDIM / BN, MDIM / BM);   // 86 x 64
    gemm_f16_kernel<<<grid, 128, SMEM_SZ>>>(Wscale, Bias, Out);
}